// round 7
// baseline (speedup 1.0000x reference)
#include <cuda_runtime.h>
#include <cuda_bf16.h>
#include <cuda_fp16.h>
#include <math.h>

// Problem constants
#define BATCH   8
#define NFREQ   513          // N_FFT/2 + 1
#define NT      4096         // frames
#define HOP     256
#define WIN     1024
#define PAD     384          // (WIN - HOP)/2
#define OUT_LEN 1048576      // (NT-1)*HOP + WIN - 2*PAD
#define ENV_EPS 1e-11f
#define FPI     3.14159265358979323846f
#define R2f     0.70710678118654752f

// Scratch: windowed frames [B][T][WIN] in fp16 (67 MB)
__device__ __half g_frames[(size_t)BATCH * NT * WIN];

// ---------------------------------------------------------------------------
// Packed f32x2 primitives. SoA across a PAIR of transforms:
//   one u64 holds (value_of_transform_A, value_of_transform_B).
// Real and imaginary parts live in SEPARATE u64 registers -> no pack/unpack
// inside the FFT math; x i / conj fold into renames & add/sub signs.
// ---------------------------------------------------------------------------
typedef unsigned long long u64c;

__device__ __forceinline__ u64c mk(float x, float y) {
    u64c r; asm("mov.b64 %0,{%1,%2};" : "=l"(r) : "f"(x), "f"(y)); return r;
}
__device__ __forceinline__ void un(u64c a, float& x, float& y) {
    asm("mov.b64 {%0,%1},%2;" : "=f"(x), "=f"(y) : "l"(a));
}
__device__ __forceinline__ u64c f2add(u64c a, u64c b) {
    u64c r; asm("add.rn.f32x2 %0,%1,%2;" : "=l"(r) : "l"(a), "l"(b)); return r;
}
__device__ __forceinline__ u64c f2mul(u64c a, u64c b) {
    u64c r; asm("mul.rn.f32x2 %0,%1,%2;" : "=l"(r) : "l"(a), "l"(b)); return r;
}
__device__ __forceinline__ u64c f2fma(u64c a, u64c b, u64c c) {
    u64c r; asm("fma.rn.f32x2 %0,%1,%2,%3;" : "=l"(r) : "l"(a), "l"(b), "l"(c)); return r;
}
#define N1C 0xBF800000BF800000ULL   // (-1.0f, -1.0f)
__device__ __forceinline__ u64c f2sub(u64c a, u64c b) { return f2fma(b, (u64c)N1C, a); }
__device__ __forceinline__ u64c f2neg(u64c a) { return f2mul(a, (u64c)N1C); }

// In-register 8-point DFT, sign +i (inverse), radix-2 DIF, on split packs.
// Output bit-reversed: slot p holds output index BR3[p] = {0,4,2,6,1,5,3,7}[p].
__device__ __forceinline__ void idft8(u64c xr[8], u64c xi[8], u64c RR, u64c RRn)
{
    u64c ur, ui, vr, vi, dr, di;
    // ---- stage h=4: twiddles 1, (R2+iR2), i, (-R2+iR2)
    ur = xr[0]; ui = xi[0]; vr = xr[4]; vi = xi[4];
    xr[0] = f2add(ur, vr); xi[0] = f2add(ui, vi);
    xr[4] = f2sub(ur, vr); xi[4] = f2sub(ui, vi);

    ur = xr[1]; ui = xi[1]; vr = xr[5]; vi = xi[5];
    dr = f2sub(ur, vr); di = f2sub(ui, vi);
    xr[1] = f2add(ur, vr); xi[1] = f2add(ui, vi);
    xr[5] = f2mul(f2sub(dr, di), RR);       // R2*(dr-di)
    xi[5] = f2mul(f2add(dr, di), RR);       // R2*(dr+di)

    ur = xr[2]; ui = xi[2]; vr = xr[6]; vi = xi[6];
    dr = f2sub(ur, vr); di = f2sub(ui, vi);
    xr[2] = f2add(ur, vr); xi[2] = f2add(ui, vi);
    xr[6] = f2neg(di);                      // i*d = (-di, dr)
    xi[6] = dr;

    ur = xr[3]; ui = xi[3]; vr = xr[7]; vi = xi[7];
    dr = f2sub(ur, vr); di = f2sub(ui, vi);
    xr[3] = f2add(ur, vr); xi[3] = f2add(ui, vi);
    xr[7] = f2mul(f2add(dr, di), RRn);      // -R2*(dr+di)
    xi[7] = f2mul(f2sub(dr, di), RR);       //  R2*(dr-di)

    // ---- stage h=2: twiddles 1, i
    #pragma unroll
    for (int g = 0; g < 8; g += 4) {
        ur = xr[g]; ui = xi[g]; vr = xr[g+2]; vi = xi[g+2];
        xr[g]   = f2add(ur, vr); xi[g]   = f2add(ui, vi);
        xr[g+2] = f2sub(ur, vr); xi[g+2] = f2sub(ui, vi);
        ur = xr[g+1]; ui = xi[g+1]; vr = xr[g+3]; vi = xi[g+3];
        dr = f2sub(ur, vr); di = f2sub(ui, vi);
        xr[g+1] = f2add(ur, vr); xi[g+1] = f2add(ui, vi);
        xr[g+3] = f2neg(di);
        xi[g+3] = dr;
    }
    // ---- stage h=1
    #pragma unroll
    for (int g = 0; g < 8; g += 2) {
        ur = xr[g]; ui = xi[g]; vr = xr[g+1]; vi = xi[g+1];
        xr[g]   = f2add(ur, vr); xi[g]   = f2add(ui, vi);
        xr[g+1] = f2sub(ur, vr); xi[g+1] = f2sub(ui, vi);
    }
}

// Twiddle apply: a *= w, with broadcast packs Tc=(c,c), Ts=(s,s), Tsn=(-s,-s).
__device__ __forceinline__ void twid(u64c& ar, u64c& ai, u64c Tc, u64c Ts, u64c Tsn)
{
    u64c nr = f2fma(ai, Tsn, f2mul(ar, Tc));
    u64c ni = f2fma(ar, Ts,  f2mul(ai, Tc));
    ar = nr; ai = ni;
}

// ---------------------------------------------------------------------------
// Kernel 1: fused Hermitian pack + 512-pt inverse FFT (3 x radix-8 Stockham).
// 256 threads, 8 frames per block as 4 SIMD2 pairs (64 threads per pair).
// ---------------------------------------------------------------------------
#define SROW 1160   // floats per pair-row (max used offset 1149; 1160%32==8 -> CF init)

__global__ void __launch_bounds__(256) istft_fft_kernel(
    const float* __restrict__ sr,   // (B, 513, 4096)
    const float* __restrict__ si,
    const float* __restrict__ win)  // (1024,)
{
    __shared__ float SmR[4 * SROW];   // (reA, reB) interleaved per element
    __shared__ float SmI[4 * SROW];
    __shared__ u64c  TWc[257];        // (c,c)    e^{+i pi k/512}
    __shared__ u64c  TWs[257];        // (s,s)
    __shared__ u64c  TWsn[257];       // (-s,-s)
    __shared__ float winS[1024];      // window * (1/1024)

    const int tid = threadIdx.x;

    for (int i = tid; i < 257; i += 256) {
        float s, c;
        __sincosf((FPI / 512.0f) * (float)i, &s, &c);
        TWc[i]  = mk(c, c);
        TWs[i]  = mk(s, s);
        TWsn[i] = mk(-s, -s);
    }
    #pragma unroll
    for (int i = tid; i < 1024; i += 256)
        winS[i] = __ldg(&win[i]) * (1.0f / 1024.0f);

    const int blk  = blockIdx.x;        // 0..4095
    const int b    = blk >> 9;          // batch
    const int tile = blk & 511;         // 8 frames per tile
    const size_t base = (size_t)b * NFREQ * NT + (size_t)tile * 8;

    // Coalesced global load: e -> (tl = e&7, k = e>>3).
    // Pair rows: row = tl>>1, within-pair slot = tl&1, element k at float 2k+slot.
    for (int e = tid; e < 8 * NFREQ; e += 256) {
        int tl = e & 7;
        int k  = e >> 3;
        size_t g = base + (size_t)k * NT + tl;
        int off = (tl >> 1) * SROW + 2 * k + (tl & 1);
        SmR[off] = sr[g];
        SmI[off] = si[g];
    }
    __syncthreads();

    const int u  = tid & 63;    // element index within transform
    const int pr = tid >> 6;    // pair 0..3 (frames 2pr, 2pr+1)
    float* R = SmR + pr * SROW;
    float* I = SmI + pr * SROW;

    const u64c RR  = mk(R2f, R2f);
    const u64c RRn = mk(-R2f, -R2f);

    constexpr int BR3[8] = {0, 4, 2, 6, 1, 5, 3, 7};

    u64c xr[8], xi[8];

    // ---- Stage 1: Hermitian pack on the fly + DFT-8 over k2 (stride 64).
    // Z[k] = E + iO (k<=256);  Z[k] = conj(E) + i conj(O) (k>256), E/O at kk=512-k.
    // conj of X[512-kk] folded into the add/sub signs (Bi enters negated).
    #pragma unroll
    for (int k2 = 0; k2 < 8; ++k2) {
        int k  = u + 64 * k2;
        int kk = (k <= 256) ? k : 512 - k;
        u64c Ar = *(const u64c*)&R[2 * kk];
        u64c Ai = *(const u64c*)&I[2 * kk];
        u64c Br = *(const u64c*)&R[2 * (512 - kk)];
        u64c Bi = *(const u64c*)&I[2 * (512 - kk)];
        if (k2 == 0 && k == 0) { Ai = 0ULL; Bi = 0ULL; }   // c2r: drop Im of bin 0
        // E = A + conj(B), Od = A - conj(B)
        u64c Er  = f2add(Ar, Br);
        u64c Ei  = f2sub(Ai, Bi);
        u64c Odr = f2sub(Ar, Br);
        u64c Odi = f2add(Ai, Bi);
        // O = Od * e^{+i pi kk/512}
        u64c Orr = f2fma(Odi, TWsn[kk], f2mul(Odr, TWc[kk]));
        u64c Oii = f2fma(Odr, TWs[kk],  f2mul(Odi, TWc[kk]));
        if (k2 < 4) {
            xr[k2] = f2sub(Er, Oii);
            xi[k2] = f2add(Ei, Orr);
        } else if (k2 > 4) {
            xr[k2] = f2add(Er, Oii);
            xi[k2] = f2sub(Orr, Ei);
        } else {  // k2 == 4: k = u+256; u==0 -> k==256 (low form), else high form
            u64c lr = f2sub(Er, Oii), li = f2add(Ei, Orr);
            u64c hr = f2add(Er, Oii), hi = f2sub(Orr, Ei);
            xr[k2] = (u == 0) ? lr : hr;
            xi[k2] = (u == 0) ? li : hi;
        }
    }
    idft8(xr, xi, RR, RRn);
    __syncthreads();                    // raw reads done before overwrite
    #pragma unroll
    for (int p = 0; p < 8; ++p) {
        int l = 9 * u + BR3[p];
        *(u64c*)&R[2 * l] = xr[p];
        *(u64c*)&I[2 * l] = xi[p];
    }
    __syncthreads();

    // ---- Stage 2: twiddle e^{2 pi i n2 k1/64}; DFT-8 over k1.
    {
        const int n2 = u & 7;
        const int k0 = u >> 3;
        #pragma unroll
        for (int k1 = 0; k1 < 8; ++k1) {
            int l = 9 * (k0 + 8 * k1) + n2;
            xr[k1] = *(const u64c*)&R[2 * l];
            xi[k1] = *(const u64c*)&I[2 * l];
        }
        #pragma unroll
        for (int k1 = 1; k1 < 8; ++k1) {
            float s, c;
            __sincosf((2.0f * FPI / 64.0f) * (float)(n2 * k1), &s, &c);
            twid(xr[k1], xi[k1], mk(c, c), mk(s, s), mk(-s, -s));
        }
        idft8(xr, xi, RR, RRn);
        __syncthreads();
        #pragma unroll
        for (int p = 0; p < 8; ++p) {
            int l = 9 * (n2 + 8 * BR3[p]) + k0;
            *(u64c*)&R[2 * l] = xr[p];
            *(u64c*)&I[2 * l] = xi[p];
        }
        __syncthreads();
    }

    // ---- Stage 3: twiddle e^{2 pi i m k0/512}; DFT-8 over k0; write frames.
    {
        const int m = u;
        #pragma unroll
        for (int k0 = 0; k0 < 8; ++k0) {
            int l = 9 * m + k0;
            xr[k0] = *(const u64c*)&R[2 * l];
            xi[k0] = *(const u64c*)&I[2 * l];
        }
        #pragma unroll
        for (int k0 = 1; k0 < 8; ++k0) {
            float s, c;
            __sincosf((2.0f * FPI / 512.0f) * (float)(m * k0), &s, &c);
            twid(xr[k0], xi[k0], mk(c, c), mk(s, s), mk(-s, -s));
        }
        idft8(xr, xi, RR, RRn);

        // z[n], n = m + 64*BR3[p]. Even/odd unpack: sample 2n = Re, 2n+1 = Im.
        const int tA = tile * 8 + 2 * pr;
        __half2* foutA = (__half2*)(g_frames + (((size_t)b * NT + tA) << 10));
        __half2* foutB = (__half2*)(g_frames + (((size_t)b * NT + tA + 1) << 10));
        #pragma unroll
        for (int p = 0; p < 8; ++p) {
            int n = m + 64 * BR3[p];
            float wx = winS[2 * n], wy = winS[2 * n + 1];
            u64c orr = f2mul(xr[p], mk(wx, wx));
            u64c oii = f2mul(xi[p], mk(wy, wy));
            float rA, rB, iA, iB;
            un(orr, rA, rB);
            un(oii, iA, iB);
            foutA[n] = __floats2half2_rn(rA, iA);
            foutB[n] = __floats2half2_rn(rB, iB);
        }
    }
}

// ---------------------------------------------------------------------------
// Kernel 2: overlap-add gather + envelope divide + crop (scalar, high-occ,
// fp16 frame reads, fp32 accumulation).
// ---------------------------------------------------------------------------
__global__ __launch_bounds__(256) void istft_ola_kernel(
    const float* __restrict__ win,
    float* __restrict__ out)
{
    int m = blockIdx.x * 256 + threadIdx.x;   // 0..OUT_LEN-1
    if (m >= OUT_LEN) return;
    int n = m + PAD;
    int q = n >> 8;
    int tlo = max(0, q - 3);
    int thi = min(NT - 1, q);

    float env = 0.0f;
    float acc[BATCH];
    #pragma unroll
    for (int b = 0; b < BATCH; ++b) acc[b] = 0.0f;

    for (int t = tlo; t <= thi; ++t) {
        int w = n - (t << 8);                 // 0..1023
        float wv = __ldg(&win[w]);
        env += wv * wv;
        #pragma unroll
        for (int b = 0; b < BATCH; ++b)
            acc[b] += __half2float(g_frames[(((size_t)b * NT + t) << 10) + w]);
    }

    float inv = 1.0f / fmaxf(env, ENV_EPS);
    #pragma unroll
    for (int b = 0; b < BATCH; ++b)
        out[(size_t)b * OUT_LEN + m] = acc[b] * inv;
}

// ---------------------------------------------------------------------------
extern "C" void kernel_launch(void* const* d_in, const int* in_sizes, int n_in,
                              void* d_out, int out_size)
{
    const float* spec_real = (const float*)d_in[0];
    const float* spec_imag = (const float*)d_in[1];
    const float* window    = (const float*)d_in[2];
    float* out = (float*)d_out;

    istft_fft_kernel<<<BATCH * (NT / 8), 256>>>(spec_real, spec_imag, window);
    istft_ola_kernel<<<OUT_LEN / 256, 256>>>(window, out);
}